// round 3
// baseline (speedup 1.0000x reference)
#include <cuda_runtime.h>
#include <math.h>

#define NB  32
#define LQ  64
#define LKV 4096
#define DM  512
#define SQRT_D 22.627416997969522f

// ---------------- scratch (static device globals; no allocation) ----------------
__device__ float g_Wqt[DM * DM];                     // Wq^T
__device__ float g_Wkt[DM * DM];                     // Wk^T
__device__ float g_Wqk[DM * DM];                     // sqrt(D) * Wk^T·... combined weight [d'][d]
__device__ float g_bqk[DM];                          // sqrt(D) * (bq · Wk)
__device__ float g_Q2[NB * LQ * DM];                 // x1 @ Wqk^T + bqk
__device__ float g_S[(size_t)NB * LQ * LKV];         // scores -> probs (in place), 33.5 MB
__device__ float g_U[NB * LQ * DM];                  // P @ x2

// ---------------- 512x512 transpose ----------------
__global__ void transpose512(const float* __restrict__ in, float* __restrict__ out) {
    __shared__ float t[32][33];
    int bx = blockIdx.x * 32, by = blockIdx.y * 32;
    int x = bx + threadIdx.x;
    #pragma unroll
    for (int i = 0; i < 32; i += 8)
        t[threadIdx.y + i][threadIdx.x] = in[(size_t)(by + threadIdx.y + i) * DM + x];
    __syncthreads();
    x = by + threadIdx.x;
    #pragma unroll
    for (int i = 0; i < 32; i += 8)
        out[(size_t)(bx + threadIdx.y + i) * DM + x] = t[threadIdx.x][threadIdx.y + i];
}

// ---------------- bqk[d'] = sqrt(D) * sum_e bq[e] * Wk[e][d'] ----------------
__global__ void bqk_kernel(const float* __restrict__ bq, const float* __restrict__ wk,
                           float* __restrict__ out) {
    int d = blockIdx.x * 64 + threadIdx.x;
    float acc = 0.f;
    for (int e = 0; e < DM; ++e)
        acc += bq[e] * wk[(size_t)e * DM + d];
    out[d] = acc * SQRT_D;
}

// ---------------- SGEMM: C[M,N] = alpha * A · op(B) (+ bias[n]) ----------------
// A: [M,K] row-major (K contiguous). BT=true: B is [N,K] (NT, dot of rows).
// BT=false: B is [K,N] row-major (NN). All of M%64==0 (or M==64), N%64==0, K%16==0.
template <bool BT>
__global__ __launch_bounds__(256)
void sgemm(const float* __restrict__ A, const float* __restrict__ Bm,
           float* __restrict__ C, const float* __restrict__ bias,
           int M, int N, int K, float alpha,
           long long strideA, long long strideB, long long strideC) {
    const float* Ab = A + (long long)blockIdx.z * strideA;
    const float* Bb = Bm + (long long)blockIdx.z * strideB;
    float* Cb = C + (long long)blockIdx.z * strideC;

    __shared__ float As[16][64];
    __shared__ float Bs[16][64];

    int tid = threadIdx.x;
    int tx = tid & 15, ty = tid >> 4;
    int m0 = blockIdx.y * 64, n0 = blockIdx.x * 64;

    float acc[4][4] = {};

    int arow = tid >> 2;             // 0..63
    int acol = (tid & 3) << 2;       // 0,4,8,12
    int brow = tid >> 4;             // 0..15 (NN)
    int bcol = (tid & 15) << 2;      // 0..60 (NN)

    for (int k0 = 0; k0 < K; k0 += 16) {
        float4 av = *(const float4*)(Ab + (long long)(m0 + arow) * K + k0 + acol);
        As[acol + 0][arow] = av.x; As[acol + 1][arow] = av.y;
        As[acol + 2][arow] = av.z; As[acol + 3][arow] = av.w;
        if (BT) {
            float4 bv = *(const float4*)(Bb + (long long)(n0 + arow) * K + k0 + acol);
            Bs[acol + 0][arow] = bv.x; Bs[acol + 1][arow] = bv.y;
            Bs[acol + 2][arow] = bv.z; Bs[acol + 3][arow] = bv.w;
        } else {
            float4 bv = *(const float4*)(Bb + (long long)(k0 + brow) * N + n0 + bcol);
            *(float4*)&Bs[brow][bcol] = bv;
        }
        __syncthreads();
        #pragma unroll
        for (int kk = 0; kk < 16; ++kk) {
            float4 a = *(const float4*)&As[kk][ty << 2];
            float4 b = *(const float4*)&Bs[kk][tx << 2];
            acc[0][0] += a.x * b.x; acc[0][1] += a.x * b.y; acc[0][2] += a.x * b.z; acc[0][3] += a.x * b.w;
            acc[1][0] += a.y * b.x; acc[1][1] += a.y * b.y; acc[1][2] += a.y * b.z; acc[1][3] += a.y * b.w;
            acc[2][0] += a.z * b.x; acc[2][1] += a.z * b.y; acc[2][2] += a.z * b.z; acc[2][3] += a.z * b.w;
            acc[3][0] += a.w * b.x; acc[3][1] += a.w * b.y; acc[3][2] += a.w * b.z; acc[3][3] += a.w * b.w;
        }
        __syncthreads();
    }

    float b0 = 0.f, b1 = 0.f, b2 = 0.f, b3 = 0.f;
    if (bias) {
        int nb = n0 + (tx << 2);
        b0 = bias[nb + 0]; b1 = bias[nb + 1]; b2 = bias[nb + 2]; b3 = bias[nb + 3];
    }
    #pragma unroll
    for (int i = 0; i < 4; ++i) {
        float4 o;
        o.x = acc[i][0] * alpha + b0;
        o.y = acc[i][1] * alpha + b1;
        o.z = acc[i][2] * alpha + b2;
        o.w = acc[i][3] * alpha + b3;
        *(float4*)(Cb + (long long)(m0 + (ty << 2) + i) * N + n0 + (tx << 2)) = o;
    }
}

// ---------------- row softmax over 4096 (in place) ----------------
__global__ __launch_bounds__(256)
void softmax4096(float* __restrict__ S) {
    float* p = S + (size_t)blockIdx.x * LKV;
    int tid = threadIdx.x;
    __shared__ float red[8];

    float v[16];
    float m = -INFINITY;
    #pragma unroll
    for (int i = 0; i < 16; ++i) {
        v[i] = p[tid + i * 256];
        m = fmaxf(m, v[i]);
    }
    #pragma unroll
    for (int o = 16; o; o >>= 1) m = fmaxf(m, __shfl_xor_sync(0xffffffffu, m, o));
    if ((tid & 31) == 0) red[tid >> 5] = m;
    __syncthreads();
    float mall = red[0];
    #pragma unroll
    for (int w = 1; w < 8; ++w) mall = fmaxf(mall, red[w]);
    __syncthreads();

    float s = 0.f;
    #pragma unroll
    for (int i = 0; i < 16; ++i) {
        v[i] = __expf(v[i] - mall);
        s += v[i];
    }
    #pragma unroll
    for (int o = 16; o; o >>= 1) s += __shfl_xor_sync(0xffffffffu, s, o);
    if ((tid & 31) == 0) red[tid >> 5] = s;
    __syncthreads();
    float st = 0.f;
    #pragma unroll
    for (int w = 0; w < 8; ++w) st += red[w];
    float inv = 1.f / st;
    #pragma unroll
    for (int i = 0; i < 16; ++i) p[tid + i * 256] = v[i] * inv;
}

// ---------------- launch ----------------
extern "C" void kernel_launch(void* const* d_in, const int* in_sizes, int n_in,
                              void* d_out, int out_size) {
    const float* x1 = (const float*)d_in[0];
    const float* x2 = (const float*)d_in[1];
    // d_in[2] = mask (unused by the reference forward)
    const float* wq = (const float*)d_in[3];
    const float* bq = (const float*)d_in[4];
    const float* wk = (const float*)d_in[5];
    // d_in[6] = bk: softmax-invariant, dropped
    const float* wv = (const float*)d_in[7];
    const float* bv = (const float*)d_in[8];
    float* out = (float*)d_out;

    float *Wqt, *Wkt, *Wqk, *bqk, *Q2, *S, *U;
    cudaGetSymbolAddress((void**)&Wqt, g_Wqt);
    cudaGetSymbolAddress((void**)&Wkt, g_Wkt);
    cudaGetSymbolAddress((void**)&Wqk, g_Wqk);
    cudaGetSymbolAddress((void**)&bqk, g_bqk);
    cudaGetSymbolAddress((void**)&Q2, g_Q2);
    cudaGetSymbolAddress((void**)&S, g_S);
    cudaGetSymbolAddress((void**)&U, g_U);

    dim3 tb(32, 8);
    transpose512<<<dim3(16, 16), tb>>>(wq, Wqt);
    transpose512<<<dim3(16, 16), tb>>>(wk, Wkt);
    bqk_kernel<<<8, 64>>>(bq, wk, bqk);

    // Wqk[d'][d] = sqrt(D) * sum_e Wk[e][d'] * Wq[e][d]   (NT: Wkt rows, Wqt rows)
    sgemm<true><<<dim3(8, 8, 1), 256>>>(Wkt, Wqt, Wqk, nullptr,
                                        512, 512, 512, SQRT_D, 0, 0, 0);

    // Q2[m][d'] = sum_d x1[m][d] * Wqk[d'][d] + bqk[d']
    sgemm<true><<<dim3(8, 32, 1), 256>>>(x1, Wqk, Q2, bqk,
                                         NB * LQ, 512, 512, 1.0f, 0, 0, 0);

    // S_b[q][t] = Q2_b[q][:] . x2_b[t][:]   (batched NT)
    sgemm<true><<<dim3(64, 1, NB), 256>>>(Q2, x2, S, nullptr,
                                          LQ, LKV, DM, 1.0f,
                                          (long long)LQ * DM, (long long)LKV * DM,
                                          (long long)LQ * LKV);

    softmax4096<<<NB * LQ, 256>>>(S);

    // U_b[q][d] = sum_t P_b[q][t] * x2_b[t][d]   (batched NN)
    sgemm<false><<<dim3(8, 1, NB), 256>>>(S, x2, U, nullptr,
                                          LQ, DM, LKV, 1.0f,
                                          (long long)LQ * LKV, (long long)LKV * DM,
                                          (long long)LQ * DM);

    // out[m][e] = sum_d U[m][d] * Wv[e][d] + bv[e]
    sgemm<true><<<dim3(8, 32, 1), 256>>>(U, wv, out, bv,
                                         NB * LQ, 512, 512, 1.0f, 0, 0, 0);
}

// round 4
// speedup vs baseline: 1.0026x; 1.0026x over previous
#include <cuda_runtime.h>
#include <math.h>

#define NB  32
#define LQ  64
#define LKV 4096
#define DM  512
#define SQRT_D 22.627416997969522f

// ---------------- scratch (static device globals; no allocation) ----------------
__device__ float g_Wqt[DM * DM];                     // Wq^T
__device__ float g_Wkt[DM * DM];                     // Wk^T
__device__ float g_Wqk[DM * DM];                     // sqrt(D) * Wk^T·... combined weight [d'][d]
__device__ float g_bqk[DM];                          // sqrt(D) * (bq · Wk)
__device__ float g_Q2[NB * LQ * DM];                 // x1 @ Wqk^T + bqk
__device__ float g_S[(size_t)NB * LQ * LKV];         // scores -> probs (in place), 33.5 MB
__device__ float g_U[NB * LQ * DM];                  // P @ x2

// ---------------- 512x512 transpose ----------------
__global__ void transpose512(const float* __restrict__ in, float* __restrict__ out) {
    __shared__ float t[32][33];
    int bx = blockIdx.x * 32, by = blockIdx.y * 32;
    int x = bx + threadIdx.x;
    #pragma unroll
    for (int i = 0; i < 32; i += 8)
        t[threadIdx.y + i][threadIdx.x] = in[(size_t)(by + threadIdx.y + i) * DM + x];
    __syncthreads();
    x = by + threadIdx.x;
    #pragma unroll
    for (int i = 0; i < 32; i += 8)
        out[(size_t)(bx + threadIdx.y + i) * DM + x] = t[threadIdx.x][threadIdx.y + i];
}

// ---------------- bqk[d'] = sqrt(D) * sum_e bq[e] * Wk[e][d'] ----------------
__global__ void bqk_kernel(const float* __restrict__ bq, const float* __restrict__ wk,
                           float* __restrict__ out) {
    int d = blockIdx.x * 64 + threadIdx.x;
    float acc = 0.f;
    for (int e = 0; e < DM; ++e)
        acc += bq[e] * wk[(size_t)e * DM + d];
    out[d] = acc * SQRT_D;
}

// ---------------- SGEMM: C[M,N] = alpha * A · op(B) (+ bias[n]) ----------------
// A: [M,K] row-major (K contiguous). BT=true: B is [N,K] (NT, dot of rows).
// BT=false: B is [K,N] row-major (NN). All of M%64==0 (or M==64), N%64==0, K%16==0.
template <bool BT>
__global__ __launch_bounds__(256)
void sgemm(const float* __restrict__ A, const float* __restrict__ Bm,
           float* __restrict__ C, const float* __restrict__ bias,
           int M, int N, int K, float alpha,
           long long strideA, long long strideB, long long strideC) {
    const float* Ab = A + (long long)blockIdx.z * strideA;
    const float* Bb = Bm + (long long)blockIdx.z * strideB;
    float* Cb = C + (long long)blockIdx.z * strideC;

    __shared__ float As[16][64];
    __shared__ float Bs[16][64];

    int tid = threadIdx.x;
    int tx = tid & 15, ty = tid >> 4;
    int m0 = blockIdx.y * 64, n0 = blockIdx.x * 64;

    float acc[4][4] = {};

    int arow = tid >> 2;             // 0..63
    int acol = (tid & 3) << 2;       // 0,4,8,12
    int brow = tid >> 4;             // 0..15 (NN)
    int bcol = (tid & 15) << 2;      // 0..60 (NN)

    for (int k0 = 0; k0 < K; k0 += 16) {
        float4 av = *(const float4*)(Ab + (long long)(m0 + arow) * K + k0 + acol);
        As[acol + 0][arow] = av.x; As[acol + 1][arow] = av.y;
        As[acol + 2][arow] = av.z; As[acol + 3][arow] = av.w;
        if (BT) {
            float4 bv = *(const float4*)(Bb + (long long)(n0 + arow) * K + k0 + acol);
            Bs[acol + 0][arow] = bv.x; Bs[acol + 1][arow] = bv.y;
            Bs[acol + 2][arow] = bv.z; Bs[acol + 3][arow] = bv.w;
        } else {
            float4 bv = *(const float4*)(Bb + (long long)(k0 + brow) * N + n0 + bcol);
            *(float4*)&Bs[brow][bcol] = bv;
        }
        __syncthreads();
        #pragma unroll
        for (int kk = 0; kk < 16; ++kk) {
            float4 a = *(const float4*)&As[kk][ty << 2];
            float4 b = *(const float4*)&Bs[kk][tx << 2];
            acc[0][0] += a.x * b.x; acc[0][1] += a.x * b.y; acc[0][2] += a.x * b.z; acc[0][3] += a.x * b.w;
            acc[1][0] += a.y * b.x; acc[1][1] += a.y * b.y; acc[1][2] += a.y * b.z; acc[1][3] += a.y * b.w;
            acc[2][0] += a.z * b.x; acc[2][1] += a.z * b.y; acc[2][2] += a.z * b.z; acc[2][3] += a.z * b.w;
            acc[3][0] += a.w * b.x; acc[3][1] += a.w * b.y; acc[3][2] += a.w * b.z; acc[3][3] += a.w * b.w;
        }
        __syncthreads();
    }

    float b0 = 0.f, b1 = 0.f, b2 = 0.f, b3 = 0.f;
    if (bias) {
        int nb = n0 + (tx << 2);
        b0 = bias[nb + 0]; b1 = bias[nb + 1]; b2 = bias[nb + 2]; b3 = bias[nb + 3];
    }
    #pragma unroll
    for (int i = 0; i < 4; ++i) {
        float4 o;
        o.x = acc[i][0] * alpha + b0;
        o.y = acc[i][1] * alpha + b1;
        o.z = acc[i][2] * alpha + b2;
        o.w = acc[i][3] * alpha + b3;
        *(float4*)(Cb + (long long)(m0 + (ty << 2) + i) * N + n0 + (tx << 2)) = o;
    }
}

// ---------------- row softmax over 4096 (in place) ----------------
__global__ __launch_bounds__(256)
void softmax4096(float* __restrict__ S) {
    float* p = S + (size_t)blockIdx.x * LKV;
    int tid = threadIdx.x;
    __shared__ float red[8];

    float v[16];
    float m = -INFINITY;
    #pragma unroll
    for (int i = 0; i < 16; ++i) {
        v[i] = p[tid + i * 256];
        m = fmaxf(m, v[i]);
    }
    #pragma unroll
    for (int o = 16; o; o >>= 1) m = fmaxf(m, __shfl_xor_sync(0xffffffffu, m, o));
    if ((tid & 31) == 0) red[tid >> 5] = m;
    __syncthreads();
    float mall = red[0];
    #pragma unroll
    for (int w = 1; w < 8; ++w) mall = fmaxf(mall, red[w]);
    __syncthreads();

    float s = 0.f;
    #pragma unroll
    for (int i = 0; i < 16; ++i) {
        v[i] = __expf(v[i] - mall);
        s += v[i];
    }
    #pragma unroll
    for (int o = 16; o; o >>= 1) s += __shfl_xor_sync(0xffffffffu, s, o);
    if ((tid & 31) == 0) red[tid >> 5] = s;
    __syncthreads();
    float st = 0.f;
    #pragma unroll
    for (int w = 0; w < 8; ++w) st += red[w];
    float inv = 1.f / st;
    #pragma unroll
    for (int i = 0; i < 16; ++i) p[tid + i * 256] = v[i] * inv;
}

// ---------------- launch ----------------
extern "C" void kernel_launch(void* const* d_in, const int* in_sizes, int n_in,
                              void* d_out, int out_size) {
    const float* x1 = (const float*)d_in[0];
    const float* x2 = (const float*)d_in[1];
    // d_in[2] = mask (unused by the reference forward)
    const float* wq = (const float*)d_in[3];
    const float* bq = (const float*)d_in[4];
    const float* wk = (const float*)d_in[5];
    // d_in[6] = bk: softmax-invariant, dropped
    const float* wv = (const float*)d_in[7];
    const float* bv = (const float*)d_in[8];
    float* out = (float*)d_out;

    float *Wqt, *Wkt, *Wqk, *bqk, *Q2, *S, *U;
    cudaGetSymbolAddress((void**)&Wqt, g_Wqt);
    cudaGetSymbolAddress((void**)&Wkt, g_Wkt);
    cudaGetSymbolAddress((void**)&Wqk, g_Wqk);
    cudaGetSymbolAddress((void**)&bqk, g_bqk);
    cudaGetSymbolAddress((void**)&Q2, g_Q2);
    cudaGetSymbolAddress((void**)&S, g_S);
    cudaGetSymbolAddress((void**)&U, g_U);

    dim3 tb(32, 8);
    transpose512<<<dim3(16, 16), tb>>>(wq, Wqt);
    transpose512<<<dim3(16, 16), tb>>>(wk, Wkt);
    bqk_kernel<<<8, 64>>>(bq, wk, bqk);

    // Wqk[d'][d] = sqrt(D) * sum_e Wk[e][d'] * Wq[e][d]   (NT: Wkt rows, Wqt rows)
    sgemm<true><<<dim3(8, 8, 1), 256>>>(Wkt, Wqt, Wqk, nullptr,
                                        512, 512, 512, SQRT_D, 0, 0, 0);

    // Q2[m][d'] = sum_d x1[m][d] * Wqk[d'][d] + bqk[d']
    sgemm<true><<<dim3(8, 32, 1), 256>>>(x1, Wqk, Q2, bqk,
                                         NB * LQ, 512, 512, 1.0f, 0, 0, 0);

    // S_b[q][t] = Q2_b[q][:] . x2_b[t][:]   (batched NT)
    sgemm<true><<<dim3(64, 1, NB), 256>>>(Q2, x2, S, nullptr,
                                          LQ, LKV, DM, 1.0f,
                                          (long long)LQ * DM, (long long)LKV * DM,
                                          (long long)LQ * LKV);

    softmax4096<<<NB * LQ, 256>>>(S);

    // U_b[q][d] = sum_t P_b[q][t] * x2_b[t][d]   (batched NN)
    sgemm<false><<<dim3(8, 1, NB), 256>>>(S, x2, U, nullptr,
                                          LQ, DM, LKV, 1.0f,
                                          (long long)LQ * LKV, (long long)LKV * DM,
                                          (long long)LQ * DM);

    // out[m][e] = sum_d U[m][d] * Wv[e][d] + bv[e]
    sgemm<true><<<dim3(8, 32, 1), 256>>>(U, wv, out, bv,
                                         NB * LQ, 512, 512, 1.0f, 0, 0, 0);
}